// round 16
// baseline (speedup 1.0000x reference)
#include <cuda_runtime.h>
#include <cstdint>
#include <math.h>

#define SENT 0x7fc00000u  // canonical NaN — sigmoid output can never equal this

// ---------------- scratch ----------------
__device__ float g_p1[4 * 256 * 256];   // pooled conv1 (n=0)
__device__ float g_p2[16 * 128 * 128];  // pooled conv2 (n=0)
__device__ float g_vlad[1024];          // vlad accum [64,16]
__device__ float g_asum[64];
__device__ float g_h0[512];             // feat0
__device__ float g_X[63 * 512];         // precomputed x-part + bias
__device__ float g_hall[64 * 512];      // h_t for t=1..63 (for k_out)
__device__ __align__(16) float g_hx[4][512];  // L2 exchange ring (16B-granule protocol)

__device__ __forceinline__ float sigm(float z) { return 1.f / (1.f + __expf(-z)); }

__device__ __forceinline__ unsigned int smem_u32(const void* p) {
    return (unsigned int)__cvta_generic_to_shared(p);
}
__device__ __forceinline__ unsigned long long pk(float a, float b) {
    unsigned long long r;
    asm("mov.b64 %0, {%1,%2};" : "=l"(r) : "f"(a), "f"(b));
    return r;
}
__device__ __forceinline__ void ffma2(unsigned long long& acc,
                                      unsigned long long a, unsigned long long b) {
    asm("fma.rn.f32x2 %0, %1, %2, %0;" : "+l"(acc) : "l"(a), "l"(b));
}
__device__ __forceinline__ float4 ldcg4(const float4* p) {
    float4 v;
    asm volatile("ld.global.cg.v4.f32 {%0,%1,%2,%3}, [%4];"
                 : "=f"(v.x), "=f"(v.y), "=f"(v.z), "=f"(v.w) : "l"(p));
    return v;
}
__device__ __forceinline__ void stcg4(float4* p, float4 v) {
    asm volatile("st.global.cg.v4.f32 [%0], {%1,%2,%3,%4};"
                 :: "l"(p), "f"(v.x), "f"(v.y), "f"(v.z), "f"(v.w) : "memory");
}
__device__ __forceinline__ int has_sent(const float4& v) {
    return (__float_as_uint(v.x) == SENT) | (__float_as_uint(v.y) == SENT) |
           (__float_as_uint(v.z) == SENT) | (__float_as_uint(v.w) == SENT);
}

// ---------------- K_xpre: X[t] = Whx @ cap0[t] + hb  (+ block0 inits scratch) ----------------
__global__ void k_xpre(const float* __restrict__ cap,
                       const float* __restrict__ hw,
                       const float* __restrict__ hb,
                       float* dout) {
    __shared__ float capt[300];
    int t = blockIdx.x, tid = threadIdx.x;
    int wid = tid >> 5, lane = tid & 31;
    if (t == 0) {
        for (int i = tid; i < 1024; i += 256) g_vlad[i] = 0.f;
        if (tid < 64) g_asum[tid] = 0.f;
        if (tid == 0) dout[0] = 0.f;
        // sentinel-init exchange slots 1..3 (slot 0 filled by k_final with h_0)
        for (int i = tid; i < 1536; i += 256)
            g_hx[1 + (i >> 9)][i & 511] = __uint_as_float(SENT);
    }
    for (int i = tid; i < 300; i += 256) capt[i] = cap[t * 300 + i];
    __syncthreads();
    for (int r = wid; r < 512; r += 8) {
        float s = 0.f;
        const float* wr = hw + (size_t)r * 812;
        for (int c = lane; c < 300; c += 32) s += wr[c] * capt[c];
#pragma unroll
        for (int o = 16; o > 0; o >>= 1) s += __shfl_xor_sync(0xffffffffu, s, o);
        if (lane == 0) g_X[t * 512 + r] = s + hb[r];
    }
}

// ---------------- K1: conv1(3->4)+relu+avgpool2, n=0; 1 oc per block (z=4) ----------------
__global__ void k_conv1(const float* __restrict__ img,
                        const float* __restrict__ w,
                        const float* __restrict__ b) {
    __shared__ float t[3][34][34];
    __shared__ float ws[27];
    __shared__ float bsv;
    int tx = threadIdx.x, ty = threadIdx.y;
    int tid = ty * 16 + tx;
    int oc = blockIdx.z;
    if (tid < 27) ws[tid] = w[oc * 27 + tid];
    if (tid == 27) bsv = b[oc];
    int gy0 = blockIdx.y * 32 - 1;
    int gx0 = blockIdx.x * 32 - 1;
    for (int i = tid; i < 3 * 34 * 34; i += 256) {
        int c = i / (34 * 34);
        int r = (i / 34) % 34;
        int q = i % 34;
        int gy = gy0 + r, gx = gx0 + q;
        float v = 0.f;
        if (gy >= 0 && gy < 512 && gx >= 0 && gx < 512)
            v = img[c * 512 * 512 + gy * 512 + gx];
        t[c][r][q] = v;
    }
    __syncthreads();
    int ly = 2 * ty, lx = 2 * tx;
    float acc = 0.f;
#pragma unroll
    for (int dy = 0; dy < 2; dy++)
#pragma unroll
        for (int dx = 0; dx < 2; dx++) {
            float s = bsv;
#pragma unroll
            for (int c = 0; c < 3; c++)
#pragma unroll
                for (int ky = 0; ky < 3; ky++)
#pragma unroll
                    for (int kx = 0; kx < 3; kx++)
                        s += t[c][ly + dy + ky][lx + dx + kx] * ws[c * 9 + ky * 3 + kx];
            acc += fmaxf(s, 0.f);
        }
    int py = blockIdx.y * 16 + ty, px = blockIdx.x * 16 + tx;
    g_p1[oc * 65536 + py * 256 + px] = acc * 0.25f;
}

// ---------------- K2: conv2(4->16)+relu+avgpool2; 1 oc per block (z=16) ----------------
__global__ void k_conv2(const float* __restrict__ w,
                        const float* __restrict__ b) {
    __shared__ float t[4][34][34];
    __shared__ float ws[36];
    __shared__ float bsv;
    int tx = threadIdx.x, ty = threadIdx.y;
    int tid = ty * 16 + tx;
    int oc = blockIdx.z;
    if (tid < 36) ws[tid] = w[oc * 36 + tid];
    if (tid == 36) bsv = b[oc];
    int gy0 = blockIdx.y * 32 - 1;
    int gx0 = blockIdx.x * 32 - 1;
    for (int i = tid; i < 4 * 34 * 34; i += 256) {
        int c = i / (34 * 34);
        int r = (i / 34) % 34;
        int q = i % 34;
        int gy = gy0 + r, gx = gx0 + q;
        float v = 0.f;
        if (gy >= 0 && gy < 256 && gx >= 0 && gx < 256)
            v = g_p1[c * 65536 + gy * 256 + gx];
        t[c][r][q] = v;
    }
    __syncthreads();
    int ly = 2 * ty, lx = 2 * tx;
    float acc = 0.f;
#pragma unroll
    for (int dy = 0; dy < 2; dy++)
#pragma unroll
        for (int dx = 0; dx < 2; dx++) {
            float s = bsv;
#pragma unroll
            for (int c = 0; c < 4; c++)
#pragma unroll
                for (int ky = 0; ky < 3; ky++)
#pragma unroll
                    for (int kx = 0; kx < 3; kx++)
                        s += t[c][ly + dy + ky][lx + dx + kx] * ws[c * 9 + ky * 3 + kx];
            acc += fmaxf(s, 0.f);
        }
    int py = blockIdx.y * 16 + ty, px = blockIdx.x * 16 + tx;
    g_p2[oc * 16384 + py * 128 + px] = acc * 0.25f;
}

// ---------------- K3: NetVLAD (128 blocks x 128 hw, 256 threads) ----------------
#define PAT 129
#define PXT 130
__global__ void k_nvlad(const float* __restrict__ nvw,
                        const float* __restrict__ nvb) {
    __shared__ float xt[16 * PXT];
    __shared__ float at[64 * PAT];
    __shared__ float ws[1024];
    __shared__ float bs[64];
    int tid = threadIdx.x;  // 256
    int h0 = blockIdx.x * 128;
    for (int i = tid; i < 1024; i += 256) ws[i] = nvw[i];
    if (tid < 64) bs[tid] = nvb[tid];
    if (tid < 128) {
        float xv[16];
#pragma unroll
        for (int c = 0; c < 16; c++) {
            float v = g_p2[c * 16384 + h0 + tid];
            xt[c * PXT + tid] = v;
            xv[c] = v;
        }
        __syncthreads();
        float a[64];
        float mx = -1e30f;
#pragma unroll
        for (int k = 0; k < 64; k++) {
            float s = bs[k];
#pragma unroll
            for (int c = 0; c < 16; c++) s += ws[k * 16 + c] * xv[c];
            a[k] = s;
            mx = fmaxf(mx, s);
        }
        float den = 0.f;
#pragma unroll
        for (int k = 0; k < 64; k++) {
            float e = __expf(a[k] - mx);
            a[k] = e;
            den += e;
        }
        float inv = 1.f / den;
#pragma unroll
        for (int k = 0; k < 64; k++) at[k * PAT + tid] = a[k] * inv;
    } else {
        __syncthreads();
    }
    __syncthreads();
    int k0 = (tid >> 3) * 2;
    int c0 = (tid & 7) * 2;
    float acc00 = 0.f, acc01 = 0.f, acc10 = 0.f, acc11 = 0.f;
    for (int h = 0; h < 128; h++) {
        float a0 = at[(k0 + 0) * PAT + h];
        float a1 = at[(k0 + 1) * PAT + h];
        float x0 = xt[(c0 + 0) * PXT + h];
        float x1 = xt[(c0 + 1) * PXT + h];
        acc00 += a0 * x0; acc01 += a0 * x1;
        acc10 += a1 * x0; acc11 += a1 * x1;
    }
    atomicAdd(&g_vlad[(k0 + 0) * 16 + c0 + 0], acc00);
    atomicAdd(&g_vlad[(k0 + 0) * 16 + c0 + 1], acc01);
    atomicAdd(&g_vlad[(k0 + 1) * 16 + c0 + 0], acc10);
    atomicAdd(&g_vlad[(k0 + 1) * 16 + c0 + 1], acc11);
    if (tid < 64) {
        float s = 0.f;
        for (int h = 0; h < 128; h++) s += at[tid * PAT + h];
        atomicAdd(&g_asum[tid], s);
    }
}

// ---------------- K4: finalize vlad + norms + fc (32 CTAs x 16 rows) ----------------
__global__ void k_final(const float* __restrict__ cent,
                        const float* __restrict__ fcw,
                        const float* __restrict__ fcb) {
    __shared__ float4 v4[256];
    __shared__ float invk[64];
    __shared__ float red[8];
    __shared__ float totS;
    float* v = (float*)v4;
    int tid = threadIdx.x;  // 256
    int wid = tid >> 5, lane = tid & 31;
    for (int i = tid; i < 1024; i += 256)
        v[i] = g_vlad[i] - g_asum[i >> 4] * cent[i];
    __syncthreads();
    if (tid < 64) {
        float s = 0.f;
#pragma unroll
        for (int c = 0; c < 16; c++) {
            float x = v[tid * 16 + c];
            s += x * x;
        }
        invk[tid] = 1.f / fmaxf(sqrtf(s), 1e-12f);
    }
    __syncthreads();
    float ss = 0.f;
    for (int i = tid; i < 1024; i += 256) {
        float x = v[i] * invk[i >> 4];
        v[i] = x;
        ss += x * x;
    }
#pragma unroll
    for (int o = 16; o > 0; o >>= 1) ss += __shfl_xor_sync(0xffffffffu, ss, o);
    if (lane == 0) red[wid] = ss;
    __syncthreads();
    if (tid == 0) {
        float t = 0.f;
#pragma unroll
        for (int i = 0; i < 8; i++) t += red[i];
        totS = 1.f / fmaxf(sqrtf(t), 1e-12f);
    }
    __syncthreads();
    float sc = totS;
#pragma unroll
    for (int k = 0; k < 2; k++) {
        int r = blockIdx.x * 16 + wid * 2 + k;
        const float4* wr = (const float4*)(fcw + (size_t)r * 1024);
        float s = 0.f;
        for (int idx = lane; idx < 256; idx += 32) {
            float4 w4 = wr[idx];
            float4 x4 = v4[idx];
            s += w4.x * x4.x + w4.y * x4.y + w4.z * x4.z + w4.w * x4.w;
        }
#pragma unroll
        for (int o = 16; o > 0; o >>= 1) s += __shfl_xor_sync(0xffffffffu, s, o);
        if (lane == 0) {
            float f = s * sc + fcb[r];
            g_h0[r] = f;
            g_hx[0][r] = f;   // exchange slot 0 = h_0
        }
    }
}

// ---------------- K5: sequential RNN core (8 CTAs, L2-sentinel exchange) ----------------
// CTA b owns rows [64b,64b+64); warp wid owns 8 rows; register weights (r10 core).
// Exchange via gmem/L2 ring g_hx[4][512] with MATCHED 16B granules:
//  - ship: warp lane 0 writes its 8 new h as 2x st.global.cg.v4 into slot (t+1)&3
//  - poll: threads 0..127 each ld.global.cg.v4 their own 16B granule of slot t&3
//    until non-sentinel (every granule is written by exactly one 16B store; L2
//    sector updates are all-or-nothing; NaN check guards any partial state),
//    then mirror to smem; one syncthreads; all warps read the mirror.
//  - reset: after poll completes (proves ALL CTAs finished step t-1), each CTA
//    sentinel-resets ITS OWN 64-float segment of slot (t-1)&3 (reused at t+3;
//    producers write it only after consuming gen t+2 -> >=2 steps of slack).
__global__ void __launch_bounds__(256, 1) k_rnn(const float* __restrict__ hw) {
    __shared__ float Xl[63 * 64];
    __shared__ __align__(16) float hmir[512];
    int b = blockIdx.x, tid = threadIdx.x;
    int wid = tid >> 5, lane = tid & 31;
    int r0g = b * 64;
    int rw8 = wid * 8;
    // weights -> registers, packed f32x2
    unsigned long long w2[8][8];
#pragma unroll
    for (int r = 0; r < 8; r++) {
        const float* rowp = hw + (size_t)(r0g + rw8 + r) * 812 + 300;
#pragma unroll
        for (int j = 0; j < 4; j++) {
            float4 v = *(const float4*)(rowp + j * 128 + 4 * lane);
            w2[r][2 * j]     = pk(v.x, v.y);
            w2[r][2 * j + 1] = pk(v.z, v.w);
        }
    }
    for (int i = tid; i < 4032; i += 256) {
        int tt = i >> 6, r = i & 63;
        Xl[i] = g_X[tt * 512 + r0g + r];
    }
    __syncthreads();
    for (int t = 0; t < 63; t++) {
        int slot = t & 3;
        // ---- poll own 16B granule, mirror to smem ----
        if (tid < 128) {
            const float4* gp = (const float4*)g_hx[slot] + tid;
            float4 v;
            do { v = ldcg4(gp); } while (has_sent(v));
            ((float4*)hmir)[tid] = v;
        }
        __syncthreads();   // mirror complete; also: all warps past previous reads
        // ---- read h_t from mirror ----
        const float4* hA = (const float4*)hmir;
        float4 v0 = hA[0 * 32 + lane];
        float4 v1 = hA[1 * 32 + lane];
        float4 v2 = hA[2 * 32 + lane];
        float4 v3 = hA[3 * 32 + lane];
        unsigned long long hp[8];
        hp[0] = pk(v0.x, v0.y); hp[1] = pk(v0.z, v0.w);
        hp[2] = pk(v1.x, v1.y); hp[3] = pk(v1.z, v1.w);
        hp[4] = pk(v2.x, v2.y); hp[5] = pk(v2.z, v2.w);
        hp[6] = pk(v3.x, v3.y); hp[7] = pk(v3.z, v3.w);
        // ---- matvec + reduce + sigmoid ----
        float s[8];
#pragma unroll
        for (int r = 0; r < 8; r++) {
            unsigned long long acc = 0ull;
#pragma unroll
            for (int p = 0; p < 8; p++) ffma2(acc, w2[r][p], hp[p]);
            float lo, hi;
            asm("mov.b64 {%0,%1}, %2;" : "=f"(lo), "=f"(hi) : "l"(acc));
            s[r] = lo + hi;
        }
#pragma unroll
        for (int o = 16; o > 0; o >>= 1) {
#pragma unroll
            for (int r = 0; r < 8; r++) s[r] += __shfl_xor_sync(0xffffffffu, s[r], o);
        }
        float hn[8];
#pragma unroll
        for (int r = 0; r < 8; r++) hn[r] = sigm(s[r] + Xl[t * 64 + rw8 + r]);
        // ---- ship FIRST (critical path): 2x 16B cg stores per warp ----
        if (t < 62 && lane == 0) {
            float4* gp = (float4*)&g_hx[(t + 1) & 3][r0g + rw8];
            stcg4(gp,     make_float4(hn[0], hn[1], hn[2], hn[3]));
            stcg4(gp + 1, make_float4(hn[4], hn[5], hn[6], hn[7]));
        }
        // persist for k_out (off critical path)
        if (lane == 8) {
            float* gp = g_hall + (t + 1) * 512 + r0g + rw8;
            *(float4*)gp       = make_float4(hn[0], hn[1], hn[2], hn[3]);
            *(float4*)(gp + 4) = make_float4(hn[4], hn[5], hn[6], hn[7]);
        }
        // ---- reset own segment of slot (t-1)&3 (safe: poll proved all CTAs past t-1) ----
        if (tid < 16) {
            float4* rp = (float4*)&g_hx[(t + 3) & 3][r0g] + tid;
            float sf = __uint_as_float(SENT);
            stcg4(rp, make_float4(sf, sf, sf, sf));
        }
        __syncthreads();   // protect hmir before next step's refill
    }
}

// ---------------- K6: output GEMM + loss ----------------
__global__ void k_out(const float* __restrict__ cap,
                      const float* __restrict__ ow,
                      const float* __restrict__ ob,
                      float* dout) {
    __shared__ float4 hv4[128];
    __shared__ float lsum;
    int t = blockIdx.x + 1;
    int tid = threadIdx.x;
    int wid = tid >> 5, lane = tid & 31;
    if (tid == 0) lsum = 0.f;
    if (tid < 128) hv4[tid] = *(const float4*)(g_hall + t * 512 + tid * 4);
    __syncthreads();
    float lacc = 0.f;
    for (int r = wid; r < 300; r += 8) {
        const float4* wr = (const float4*)(ow + (size_t)r * 512);
        float s = 0.f;
        for (int idx = lane; idx < 128; idx += 32) {
            float4 w4 = wr[idx];
            float4 h4 = hv4[idx];
            s += w4.x * h4.x + w4.y * h4.y + w4.z * h4.z + w4.w * h4.w;
        }
#pragma unroll
        for (int o = 16; o > 0; o >>= 1) s += __shfl_xor_sync(0xffffffffu, s, o);
        if (lane == 0) {
            float y = sigm(s + ob[r]);
            float d = y - cap[t * 300 + r];
            lacc += d * d;
        }
    }
    if (lane == 0) atomicAdd(&lsum, lacc);
    __syncthreads();
    if (tid == 0) atomicAdd(dout, lsum * (1.f / 19200.f));
}

// ---------------- launcher ----------------
extern "C" void kernel_launch(void* const* d_in, const int* in_sizes, int n_in,
                              void* d_out, int out_size) {
    const float* img     = (const float*)d_in[0];
    const float* cap     = (const float*)d_in[1];
    const float* conv1_w = (const float*)d_in[2];
    const float* conv1_b = (const float*)d_in[3];
    const float* conv2_w = (const float*)d_in[4];
    const float* conv2_b = (const float*)d_in[5];
    const float* cent    = (const float*)d_in[6];
    const float* nv_w    = (const float*)d_in[7];
    const float* nv_b    = (const float*)d_in[8];
    const float* fc_w    = (const float*)d_in[9];
    const float* fc_b    = (const float*)d_in[10];
    const float* hid_w   = (const float*)d_in[11];
    const float* hid_b   = (const float*)d_in[12];
    const float* out_w   = (const float*)d_in[13];
    const float* out_b   = (const float*)d_in[14];
    float* dout = (float*)d_out;

    k_xpre<<<63, 256>>>(cap, hid_w, hid_b, dout);
    k_conv1<<<dim3(16, 16, 4), dim3(16, 16)>>>(img, conv1_w, conv1_b);
    k_conv2<<<dim3(8, 8, 16), dim3(16, 16)>>>(conv2_w, conv2_b);
    k_nvlad<<<128, 256>>>(nv_w, nv_b);
    k_final<<<32, 256>>>(cent, fc_w, fc_b);
    k_rnn<<<8, 256>>>(hid_w);
    k_out<<<63, 256>>>(cap, out_w, out_b, dout);
}

// round 17
// speedup vs baseline: 1.9950x; 1.9950x over previous
#include <cuda_runtime.h>
#include <cstdint>
#include <math.h>

#define SENT 0x7fc00000u  // canonical NaN — sigmoid output can never equal this

// ---------------- scratch ----------------
__device__ float g_p1[4 * 256 * 256];   // pooled conv1 (n=0)
__device__ float g_p2[16 * 128 * 128];  // pooled conv2 (n=0)
__device__ float g_vlad[1024];          // vlad accum [64,16]
__device__ float g_asum[64];
__device__ float g_h0[512];             // feat0
__device__ float g_X[63 * 512];         // precomputed x-part + bias
__device__ float g_hall[64 * 512];      // h_t for t=1..63

__device__ __forceinline__ float sigm(float z) { return 1.f / (1.f + __expf(-z)); }

__device__ __forceinline__ unsigned int smem_u32(const void* p) {
    return (unsigned int)__cvta_generic_to_shared(p);
}
__device__ __forceinline__ unsigned long long pk(float a, float b) {
    unsigned long long r;
    asm("mov.b64 %0, {%1,%2};" : "=l"(r) : "f"(a), "f"(b));
    return r;
}
__device__ __forceinline__ void ffma2(unsigned long long& acc,
                                      unsigned long long a, unsigned long long b) {
    asm("fma.rn.f32x2 %0, %1, %2, %0;" : "+l"(acc) : "l"(a), "l"(b));
}
__device__ __forceinline__ float4 ldvol4(unsigned int a) {
    float4 v;
    asm volatile("ld.volatile.shared.v4.f32 {%0,%1,%2,%3}, [%4];"
                 : "=f"(v.x), "=f"(v.y), "=f"(v.z), "=f"(v.w) : "r"(a));
    return v;
}
__device__ __forceinline__ int has_sent(const float4& v) {
    return (__float_as_uint(v.x) == SENT) | (__float_as_uint(v.y) == SENT) |
           (__float_as_uint(v.z) == SENT) | (__float_as_uint(v.w) == SENT);
}
#define CLUSTER_SYNC() do { \
    asm volatile("barrier.cluster.arrive.aligned;" ::: "memory"); \
    asm volatile("barrier.cluster.wait.aligned;"   ::: "memory"); \
} while (0)

// ---------------- K_xpre: row-blocked X[t] = Whx @ cap0[t] + hb ----------------
// 32 blocks x 16 rows; cap0[0..62] staged once in smem; weights in registers.
__global__ void k_xpre(const float* __restrict__ cap,
                       const float* __restrict__ hw,
                       const float* __restrict__ hb,
                       float* dout) {
    extern __shared__ float capS[];   // [63*300]
    int bid = blockIdx.x, tid = threadIdx.x;
    int wid = tid >> 5, lane = tid & 31;
    if (bid == 0) {
        for (int i = tid; i < 1024; i += 256) g_vlad[i] = 0.f;
        if (tid < 64) g_asum[tid] = 0.f;
        if (tid == 0) dout[0] = 0.f;
    }
    for (int i = tid; i < 63 * 300; i += 256) capS[i] = cap[i];
    int g0 = bid * 16 + wid * 2;
    int g1 = g0 + 1;
    float w0[10], w1[10];
#pragma unroll
    for (int i = 0; i < 10; i++) {
        int c = lane + 32 * i;
        w0[i] = (c < 300) ? hw[(size_t)g0 * 812 + c] : 0.f;
        w1[i] = (c < 300) ? hw[(size_t)g1 * 812 + c] : 0.f;
    }
    float b0 = hb[g0], b1 = hb[g1];
    __syncthreads();
    for (int t = 0; t < 63; t++) {
        const float* ct = capS + t * 300;
        float s0 = 0.f, s1 = 0.f;
#pragma unroll
        for (int i = 0; i < 10; i++) {
            int c = lane + 32 * i;
            float cv = (c < 300) ? ct[c] : 0.f;
            s0 += w0[i] * cv;
            s1 += w1[i] * cv;
        }
#pragma unroll
        for (int o = 16; o > 0; o >>= 1) {
            s0 += __shfl_xor_sync(0xffffffffu, s0, o);
            s1 += __shfl_xor_sync(0xffffffffu, s1, o);
        }
        if (lane == 0) {
            g_X[t * 512 + g0] = s0 + b0;
            g_X[t * 512 + g1] = s1 + b1;
        }
    }
}

// ---------------- K1: conv1(3->4)+relu+avgpool2, n=0; 1 oc per block (z=4) ----------------
__global__ void k_conv1(const float* __restrict__ img,
                        const float* __restrict__ w,
                        const float* __restrict__ b) {
    __shared__ float t[3][34][34];
    __shared__ float ws[27];
    __shared__ float bsv;
    int tx = threadIdx.x, ty = threadIdx.y;
    int tid = ty * 16 + tx;
    int oc = blockIdx.z;
    if (tid < 27) ws[tid] = w[oc * 27 + tid];
    if (tid == 27) bsv = b[oc];
    int gy0 = blockIdx.y * 32 - 1;
    int gx0 = blockIdx.x * 32 - 1;
    for (int i = tid; i < 3 * 34 * 34; i += 256) {
        int c = i / (34 * 34);
        int r = (i / 34) % 34;
        int q = i % 34;
        int gy = gy0 + r, gx = gx0 + q;
        float v = 0.f;
        if (gy >= 0 && gy < 512 && gx >= 0 && gx < 512)
            v = img[c * 512 * 512 + gy * 512 + gx];
        t[c][r][q] = v;
    }
    __syncthreads();
    int ly = 2 * ty, lx = 2 * tx;
    float acc = 0.f;
#pragma unroll
    for (int dy = 0; dy < 2; dy++)
#pragma unroll
        for (int dx = 0; dx < 2; dx++) {
            float s = bsv;
#pragma unroll
            for (int c = 0; c < 3; c++)
#pragma unroll
                for (int ky = 0; ky < 3; ky++)
#pragma unroll
                    for (int kx = 0; kx < 3; kx++)
                        s += t[c][ly + dy + ky][lx + dx + kx] * ws[c * 9 + ky * 3 + kx];
            acc += fmaxf(s, 0.f);
        }
    int py = blockIdx.y * 16 + ty, px = blockIdx.x * 16 + tx;
    g_p1[oc * 65536 + py * 256 + px] = acc * 0.25f;
}

// ---------------- K2: conv2(4->16)+relu+avgpool2; 1 oc per block (z=16) ----------------
__global__ void k_conv2(const float* __restrict__ w,
                        const float* __restrict__ b) {
    __shared__ float t[4][34][34];
    __shared__ float ws[36];
    __shared__ float bsv;
    int tx = threadIdx.x, ty = threadIdx.y;
    int tid = ty * 16 + tx;
    int oc = blockIdx.z;
    if (tid < 36) ws[tid] = w[oc * 36 + tid];
    if (tid == 36) bsv = b[oc];
    int gy0 = blockIdx.y * 32 - 1;
    int gx0 = blockIdx.x * 32 - 1;
    for (int i = tid; i < 4 * 34 * 34; i += 256) {
        int c = i / (34 * 34);
        int r = (i / 34) % 34;
        int q = i % 34;
        int gy = gy0 + r, gx = gx0 + q;
        float v = 0.f;
        if (gy >= 0 && gy < 256 && gx >= 0 && gx < 256)
            v = g_p1[c * 65536 + gy * 256 + gx];
        t[c][r][q] = v;
    }
    __syncthreads();
    int ly = 2 * ty, lx = 2 * tx;
    float acc = 0.f;
#pragma unroll
    for (int dy = 0; dy < 2; dy++)
#pragma unroll
        for (int dx = 0; dx < 2; dx++) {
            float s = bsv;
#pragma unroll
            for (int c = 0; c < 4; c++)
#pragma unroll
                for (int ky = 0; ky < 3; ky++)
#pragma unroll
                    for (int kx = 0; kx < 3; kx++)
                        s += t[c][ly + dy + ky][lx + dx + kx] * ws[c * 9 + ky * 3 + kx];
            acc += fmaxf(s, 0.f);
        }
    int py = blockIdx.y * 16 + ty, px = blockIdx.x * 16 + tx;
    g_p2[oc * 16384 + py * 128 + px] = acc * 0.25f;
}

// ---------------- K3: NetVLAD (128 blocks x 128 hw, 256 threads) ----------------
#define PAT 129
#define PXT 130
__global__ void k_nvlad(const float* __restrict__ nvw,
                        const float* __restrict__ nvb) {
    __shared__ float xt[16 * PXT];
    __shared__ float at[64 * PAT];
    __shared__ float ws[1024];
    __shared__ float bs[64];
    int tid = threadIdx.x;  // 256
    int h0 = blockIdx.x * 128;
    for (int i = tid; i < 1024; i += 256) ws[i] = nvw[i];
    if (tid < 64) bs[tid] = nvb[tid];
    if (tid < 128) {
        float xv[16];
#pragma unroll
        for (int c = 0; c < 16; c++) {
            float v = g_p2[c * 16384 + h0 + tid];
            xt[c * PXT + tid] = v;
            xv[c] = v;
        }
        __syncthreads();
        float a[64];
        float mx = -1e30f;
#pragma unroll
        for (int k = 0; k < 64; k++) {
            float s = bs[k];
#pragma unroll
            for (int c = 0; c < 16; c++) s += ws[k * 16 + c] * xv[c];
            a[k] = s;
            mx = fmaxf(mx, s);
        }
        float den = 0.f;
#pragma unroll
        for (int k = 0; k < 64; k++) {
            float e = __expf(a[k] - mx);
            a[k] = e;
            den += e;
        }
        float inv = 1.f / den;
#pragma unroll
        for (int k = 0; k < 64; k++) at[k * PAT + tid] = a[k] * inv;
    } else {
        __syncthreads();
    }
    __syncthreads();
    int k0 = (tid >> 3) * 2;
    int c0 = (tid & 7) * 2;
    float acc00 = 0.f, acc01 = 0.f, acc10 = 0.f, acc11 = 0.f;
#pragma unroll 4
    for (int h = 0; h < 128; h++) {
        float a0 = at[(k0 + 0) * PAT + h];
        float a1 = at[(k0 + 1) * PAT + h];
        float x0 = xt[(c0 + 0) * PXT + h];
        float x1 = xt[(c0 + 1) * PXT + h];
        acc00 += a0 * x0; acc01 += a0 * x1;
        acc10 += a1 * x0; acc11 += a1 * x1;
    }
    atomicAdd(&g_vlad[(k0 + 0) * 16 + c0 + 0], acc00);
    atomicAdd(&g_vlad[(k0 + 0) * 16 + c0 + 1], acc01);
    atomicAdd(&g_vlad[(k0 + 1) * 16 + c0 + 0], acc10);
    atomicAdd(&g_vlad[(k0 + 1) * 16 + c0 + 1], acc11);
    if (tid < 64) {
        float s = 0.f;
        for (int h = 0; h < 128; h++) s += at[tid * PAT + h];
        atomicAdd(&g_asum[tid], s);
    }
}

// ---------------- K4: finalize vlad + norms + fc (32 CTAs x 16 rows) ----------------
__global__ void k_final(const float* __restrict__ cent,
                        const float* __restrict__ fcw,
                        const float* __restrict__ fcb) {
    __shared__ float4 v4[256];
    __shared__ float invk[64];
    __shared__ float red[8];
    __shared__ float totS;
    float* v = (float*)v4;
    int tid = threadIdx.x;  // 256
    int wid = tid >> 5, lane = tid & 31;
    for (int i = tid; i < 1024; i += 256)
        v[i] = g_vlad[i] - g_asum[i >> 4] * cent[i];
    __syncthreads();
    if (tid < 64) {
        float s = 0.f;
#pragma unroll
        for (int c = 0; c < 16; c++) {
            float x = v[tid * 16 + c];
            s += x * x;
        }
        invk[tid] = 1.f / fmaxf(sqrtf(s), 1e-12f);
    }
    __syncthreads();
    float ss = 0.f;
    for (int i = tid; i < 1024; i += 256) {
        float x = v[i] * invk[i >> 4];
        v[i] = x;
        ss += x * x;
    }
#pragma unroll
    for (int o = 16; o > 0; o >>= 1) ss += __shfl_xor_sync(0xffffffffu, ss, o);
    if (lane == 0) red[wid] = ss;
    __syncthreads();
    if (tid == 0) {
        float t = 0.f;
#pragma unroll
        for (int i = 0; i < 8; i++) t += red[i];
        totS = 1.f / fmaxf(sqrtf(t), 1e-12f);
    }
    __syncthreads();
    float sc = totS;
#pragma unroll
    for (int k = 0; k < 2; k++) {
        int r = blockIdx.x * 16 + wid * 2 + k;
        const float4* wr = (const float4*)(fcw + (size_t)r * 1024);
        float s = 0.f;
        for (int idx = lane; idx < 256; idx += 32) {
            float4 w4 = wr[idx];
            float4 x4 = v4[idx];
            s += w4.x * x4.x + w4.y * x4.y + w4.z * x4.z + w4.w * x4.w;
        }
#pragma unroll
        for (int o = 16; o > 0; o >>= 1) s += __shfl_xor_sync(0xffffffffu, s, o);
        if (lane == 0) g_h0[r] = s * sc + fcb[r];
    }
}

// ---------------- K5: sequential RNN core (r10 champion + split-ship) ----------------
// 8-CTA cluster, register weights, sentinel-NaN poll, 4-buffer ring, one sync/step.
// NEW: rows 0-3 computed+shipped before rows 4-7 (crossing starts earlier);
// mapa hoisted out of the loop (linear offsets within peer window).
__global__ void __launch_bounds__(256, 1) __cluster_dims__(8, 1, 1)
k_rnn(const float* __restrict__ hw) {
    __shared__ float Xl[63 * 64];
    __shared__ __align__(16) float hbuf[4][512];
    int b = blockIdx.x, tid = threadIdx.x;
    int wid = tid >> 5, lane = tid & 31;
    int r0g = b * 64;
    int rw8 = wid * 8;
    unsigned long long w2[8][8];
#pragma unroll
    for (int r = 0; r < 8; r++) {
        const float* rowp = hw + (size_t)(r0g + rw8 + r) * 812 + 300;
#pragma unroll
        for (int j = 0; j < 4; j++) {
            float4 v = *(const float4*)(rowp + j * 128 + 4 * lane);
            w2[r][2 * j]     = pk(v.x, v.y);
            w2[r][2 * j + 1] = pk(v.z, v.w);
        }
    }
    for (int i = tid; i < 4032; i += 256) {
        int tt = i >> 6, r = i & 63;
        Xl[i] = g_X[tt * 512 + r0g + r];
    }
    for (int i = tid; i < 512; i += 256) {
        hbuf[0][i] = g_h0[i];
        hbuf[1][i] = __uint_as_float(SENT);
        hbuf[2][i] = __uint_as_float(SENT);
        hbuf[3][i] = __uint_as_float(SENT);
    }
    // hoisted remote base: rank `lane`'s hbuf[0], offset by slot*2048 + row*4 later
    unsigned int rbase = 0;
    if (lane < 8) {
        unsigned int laddr = smem_u32(&hbuf[0][r0g + rw8]);
        asm volatile("mapa.shared::cluster.u32 %0, %1, %2;"
                     : "=r"(rbase) : "r"(laddr), "r"(lane));
    }
    __syncthreads();
    CLUSTER_SYNC();   // peers' buffers initialized before any remote store
    for (int t = 0; t < 63; t++) {
        int idx = t & 3;
        unsigned int a0 = smem_u32((const float4*)hbuf[idx] + 0 * 32 + lane);
        unsigned int a1 = smem_u32((const float4*)hbuf[idx] + 1 * 32 + lane);
        unsigned int a2 = smem_u32((const float4*)hbuf[idx] + 2 * 32 + lane);
        unsigned int a3 = smem_u32((const float4*)hbuf[idx] + 3 * 32 + lane);
        float4 v0, v1, v2, v3;
        do {
            v0 = ldvol4(a0); v1 = ldvol4(a1); v2 = ldvol4(a2); v3 = ldvol4(a3);
        } while (has_sent(v0) | has_sent(v1) | has_sent(v2) | has_sent(v3));
        __syncthreads();   // all warps done reading b[idx] and b[(t-1)&3]
        unsigned long long hp[8];
        hp[0] = pk(v0.x, v0.y); hp[1] = pk(v0.z, v0.w);
        hp[2] = pk(v1.x, v1.y); hp[3] = pk(v1.z, v1.w);
        hp[4] = pk(v2.x, v2.y); hp[5] = pk(v2.z, v2.w);
        hp[6] = pk(v3.x, v3.y); hp[7] = pk(v3.z, v3.w);
        unsigned int shipbase = rbase + ((unsigned)((t + 1) & 3)) * 2048u;
        float hn[8];
        // ---- group 1: rows 0-3 ----
        {
            float s[4];
#pragma unroll
            for (int r = 0; r < 4; r++) {
                unsigned long long acc = 0ull;
#pragma unroll
                for (int p = 0; p < 8; p++) ffma2(acc, w2[r][p], hp[p]);
                float lo, hi;
                asm("mov.b64 {%0,%1}, %2;" : "=f"(lo), "=f"(hi) : "l"(acc));
                s[r] = lo + hi;
            }
#pragma unroll
            for (int o = 16; o > 0; o >>= 1) {
#pragma unroll
                for (int r = 0; r < 4; r++) s[r] += __shfl_xor_sync(0xffffffffu, s[r], o);
            }
#pragma unroll
            for (int r = 0; r < 4; r++) hn[r] = sigm(s[r] + Xl[t * 64 + rw8 + r]);
            if (t < 62 && lane < 8) {
                asm volatile("st.shared::cluster.b64 [%0], %1;"
                             :: "r"(shipbase), "l"(pk(hn[0], hn[1])) : "memory");
                asm volatile("st.shared::cluster.b64 [%0], %1;"
                             :: "r"(shipbase + 8), "l"(pk(hn[2], hn[3])) : "memory");
            }
        }
        // ---- group 2: rows 4-7 ----
        {
            float s[4];
#pragma unroll
            for (int r = 0; r < 4; r++) {
                unsigned long long acc = 0ull;
#pragma unroll
                for (int p = 0; p < 8; p++) ffma2(acc, w2[4 + r][p], hp[p]);
                float lo, hi;
                asm("mov.b64 {%0,%1}, %2;" : "=f"(lo), "=f"(hi) : "l"(acc));
                s[r] = lo + hi;
            }
#pragma unroll
            for (int o = 16; o > 0; o >>= 1) {
#pragma unroll
                for (int r = 0; r < 4; r++) s[r] += __shfl_xor_sync(0xffffffffu, s[r], o);
            }
#pragma unroll
            for (int r = 0; r < 4; r++) hn[4 + r] = sigm(s[r] + Xl[t * 64 + rw8 + 4 + r]);
            if (t < 62 && lane < 8) {
                asm volatile("st.shared::cluster.b64 [%0], %1;"
                             :: "r"(shipbase + 16), "l"(pk(hn[4], hn[5])) : "memory");
                asm volatile("st.shared::cluster.b64 [%0], %1;"
                             :: "r"(shipbase + 24), "l"(pk(hn[6], hn[7])) : "memory");
            }
        }
        if (lane == 8) {
            float* gp = g_hall + (t + 1) * 512 + r0g + rw8;
            *(float4*)gp       = make_float4(hn[0], hn[1], hn[2], hn[3]);
            *(float4*)(gp + 4) = make_float4(hn[4], hn[5], hn[6], hn[7]);
        }
        {
            int pidx = (t + 3) & 3;  // == (t-1)&3
            for (int i = tid; i < 512; i += 256)
                hbuf[pidx][i] = __uint_as_float(SENT);
        }
    }
    CLUSTER_SYNC();   // no CTA exits while peers might still write its smem
}

// ---------------- K6: row-blocked output GEMM + loss (50 blocks x 6 rows) ----------------
__global__ void k_out(const float* __restrict__ cap,
                      const float* __restrict__ ow,
                      const float* __restrict__ ob,
                      float* dout) {
    __shared__ __align__(16) float ow6[6 * 512];
    __shared__ float obs[6];
    __shared__ float lsum;
    int bid = blockIdx.x, tid = threadIdx.x;
    int wid = tid >> 5, lane = tid & 31;
    int rows0 = bid * 6;
    if (tid == 0) lsum = 0.f;
    if (tid < 6) obs[tid] = ob[rows0 + tid];
    for (int i = tid; i < 6 * 512; i += 256)
        ow6[i] = ow[(size_t)(rows0 + i / 512) * 512 + (i & 511)];
    __syncthreads();
    const float4* ow4 = (const float4*)ow6;
    float lacc = 0.f;
    for (int k = 0; k < 8; k++) {
        int t = 1 + wid + 8 * k;
        if (t > 63) break;
        const float4* hA = (const float4*)(g_hall + t * 512);
        float4 h0 = hA[0 * 32 + lane];
        float4 h1 = hA[1 * 32 + lane];
        float4 h2 = hA[2 * 32 + lane];
        float4 h3 = hA[3 * 32 + lane];
#pragma unroll
        for (int r = 0; r < 6; r++) {
            const float4* wr = ow4 + r * 128;
            float4 w0 = wr[0 * 32 + lane];
            float4 w1 = wr[1 * 32 + lane];
            float4 w2 = wr[2 * 32 + lane];
            float4 w3 = wr[3 * 32 + lane];
            float s = w0.x * h0.x + w0.y * h0.y + w0.z * h0.z + w0.w * h0.w
                    + w1.x * h1.x + w1.y * h1.y + w1.z * h1.z + w1.w * h1.w
                    + w2.x * h2.x + w2.y * h2.y + w2.z * h2.z + w2.w * h2.w
                    + w3.x * h3.x + w3.y * h3.y + w3.z * h3.z + w3.w * h3.w;
#pragma unroll
            for (int o = 16; o > 0; o >>= 1) s += __shfl_xor_sync(0xffffffffu, s, o);
            if (lane == 0) {
                float y = sigm(s + obs[r]);
                float d = y - cap[t * 300 + rows0 + r];
                lacc += d * d;
            }
        }
    }
    if (lane == 0) atomicAdd(&lsum, lacc);
    __syncthreads();
    if (tid == 0) atomicAdd(dout, lsum * (1.f / 19200.f));
}

// ---------------- launcher ----------------
extern "C" void kernel_launch(void* const* d_in, const int* in_sizes, int n_in,
                              void* d_out, int out_size) {
    const float* img     = (const float*)d_in[0];
    const float* cap     = (const float*)d_in[1];
    const float* conv1_w = (const float*)d_in[2];
    const float* conv1_b = (const float*)d_in[3];
    const float* conv2_w = (const float*)d_in[4];
    const float* conv2_b = (const float*)d_in[5];
    const float* cent    = (const float*)d_in[6];
    const float* nv_w    = (const float*)d_in[7];
    const float* nv_b    = (const float*)d_in[8];
    const float* fc_w    = (const float*)d_in[9];
    const float* fc_b    = (const float*)d_in[10];
    const float* hid_w   = (const float*)d_in[11];
    const float* hid_b   = (const float*)d_in[12];
    const float* out_w   = (const float*)d_in[13];
    const float* out_b   = (const float*)d_in[14];
    float* dout = (float*)d_out;

    size_t xpre_smem = (size_t)63 * 300 * sizeof(float);  // 75600 B
    static bool attr_set = false;
    if (!attr_set) {
        cudaFuncSetAttribute(k_xpre, cudaFuncAttributeMaxDynamicSharedMemorySize,
                             (int)(xpre_smem + 256));
        attr_set = true;
    }

    k_xpre<<<32, 256, xpre_smem>>>(cap, hid_w, hid_b, dout);
    k_conv1<<<dim3(16, 16, 4), dim3(16, 16)>>>(img, conv1_w, conv1_b);
    k_conv2<<<dim3(8, 8, 16), dim3(16, 16)>>>(conv2_w, conv2_b);
    k_nvlad<<<128, 256>>>(nv_w, nv_b);
    k_final<<<32, 256>>>(cent, fc_w, fc_b);
    k_rnn<<<8, 256>>>(hid_w);
    k_out<<<50, 256>>>(cap, out_w, out_b, dout);
}